// round 2
// baseline (speedup 1.0000x reference)
#include <cuda_runtime.h>
#include <math.h>

#define NT 8192
#define DM 1024
#define FF 4096
#define NE 8
#define TOTAL_ROWS (NT * 2)

// ---- scratch (device globals; no runtime allocation allowed) ----
__device__ int   g_cnt[NE];
__device__ int   g_off[NE];
__device__ int   g_tok[NE * NT];
__device__ float g_w  [NE * NT];
// padded by 128 rows so OOB-tile A-loads in GEMM2 stay in-bounds
__device__ __align__(16) float g_h[(size_t)(TOTAL_ROWS + 128) * FF];

// ---------------------------------------------------------------
// zero expert counts + zero the output buffer (poisoned by harness)
// ---------------------------------------------------------------
__global__ void zero_kernel(float* __restrict__ out) {
    int i = blockIdx.x * blockDim.x + threadIdx.x;
    if (i < NE) g_cnt[i] = 0;
    float4* o4 = reinterpret_cast<float4*>(out);
    const int n4 = NT * DM / 4;
    for (int j = i; j < n4; j += gridDim.x * blockDim.x)
        o4[j] = make_float4(0.f, 0.f, 0.f, 0.f);
}

// ---------------------------------------------------------------
// gate: one warp per token. logits = x@Wg + bg, softmax, top-2,
// renormalize, append (token, weight) to per-expert list.
// ---------------------------------------------------------------
__global__ void gate_kernel(const float* __restrict__ x,
                            const float* __restrict__ Wg,
                            const float* __restrict__ bg) {
    int gtid = blockIdx.x * blockDim.x + threadIdx.x;
    int t    = gtid >> 5;
    int lane = gtid & 31;
    if (t >= NT) return;

    const float* xr = x + (size_t)t * DM;
    float acc[NE];
#pragma unroll
    for (int e = 0; e < NE; e++) acc[e] = 0.f;

    for (int k = lane; k < DM; k += 32) {
        float xv = xr[k];
        const float* wr = Wg + k * NE;
#pragma unroll
        for (int e = 0; e < NE; e++) acc[e] += xv * wr[e];
    }
#pragma unroll
    for (int s = 16; s > 0; s >>= 1) {
#pragma unroll
        for (int e = 0; e < NE; e++)
            acc[e] += __shfl_xor_sync(0xffffffffu, acc[e], s);
    }

    if (lane == 0) {
#pragma unroll
        for (int e = 0; e < NE; e++) acc[e] += bg[e];
        float mx = acc[0];
#pragma unroll
        for (int e = 1; e < NE; e++) mx = fmaxf(mx, acc[e]);
        float s = 0.f;
#pragma unroll
        for (int e = 0; e < NE; e++) { acc[e] = expf(acc[e] - mx); s += acc[e]; }
        float inv = 1.f / s;
#pragma unroll
        for (int e = 0; e < NE; e++) acc[e] *= inv;

        int i0 = 0;
#pragma unroll
        for (int e = 1; e < NE; e++) if (acc[e] > acc[i0]) i0 = e;
        int i1 = (i0 == 0) ? 1 : 0;
#pragma unroll
        for (int e = 0; e < NE; e++)
            if (e != i0 && acc[e] > acc[i1]) i1 = e;

        float s2 = acc[i0] + acc[i1] + 1e-9f;
        float w0 = acc[i0] / s2;
        float w1 = acc[i1] / s2;

        int p0 = atomicAdd(&g_cnt[i0], 1);
        g_tok[i0 * NT + p0] = t;  g_w[i0 * NT + p0] = w0;
        int p1 = atomicAdd(&g_cnt[i1], 1);
        g_tok[i1 * NT + p1] = t;  g_w[i1 * NT + p1] = w1;
    }
}

// exclusive prefix sum over the 8 counts
__global__ void offsets_kernel() {
    if (threadIdx.x == 0 && blockIdx.x == 0) {
        int s = 0;
#pragma unroll
        for (int e = 0; e < NE; e++) { g_off[e] = s; s += g_cnt[e]; }
    }
}

// ---------------------------------------------------------------
// GEMM1 + bias + exact GELU:  h = gelu(x[tok]@W1[e] + b1[e])
// 128x128 tile, 256 threads, 8x8 microtile, K-tile = 8, fp32.
// ---------------------------------------------------------------
__global__ __launch_bounds__(256)
void ffn1_kernel(const float* __restrict__ x,
                 const float* __restrict__ W1,
                 const float* __restrict__ b1) {
    const int e     = blockIdx.z;
    const int cnt   = g_cnt[e];
    const int mbase = blockIdx.y * 128;
    if (mbase >= cnt) return;
    const int nbase = blockIdx.x * 128;

    __shared__ int   stok[128];
    __shared__ float As[8][129];
    __shared__ float Bs[8][128];

    const int tid = threadIdx.x;
    if (tid < 128) {
        int mi = mbase + tid;
        stok[tid] = (mi < cnt) ? g_tok[e * NT + mi] : g_tok[e * NT + mbase];
    }
    __syncthreads();

    const int tx = tid & 15, ty = tid >> 4;
    float acc[8][8];
#pragma unroll
    for (int i = 0; i < 8; i++)
#pragma unroll
        for (int j = 0; j < 8; j++) acc[i][j] = 0.f;

    const int am = tid >> 1;
    const int ak = (tid & 1) * 4;
    const int bk = tid >> 5;
    const int bn = (tid & 31) * 4;
    const float*  W1e  = W1 + (size_t)e * DM * FF;
    const size_t  arow = (size_t)stok[am] * DM;

    for (int kt = 0; kt < DM; kt += 8) {
        float4 av = *(const float4*)(x + arow + kt + ak);
        float4 bv = *(const float4*)(W1e + (size_t)(kt + bk) * FF + nbase + bn);
        __syncthreads();
        As[ak + 0][am] = av.x; As[ak + 1][am] = av.y;
        As[ak + 2][am] = av.z; As[ak + 3][am] = av.w;
        *(float4*)&Bs[bk][bn] = bv;
        __syncthreads();
#pragma unroll
        for (int kk = 0; kk < 8; kk++) {
            float a_[8], b_[8];
#pragma unroll
            for (int i = 0; i < 8; i++) a_[i] = As[kk][ty * 8 + i];
#pragma unroll
            for (int j = 0; j < 8; j++) b_[j] = Bs[kk][tx * 8 + j];
#pragma unroll
            for (int i = 0; i < 8; i++)
#pragma unroll
                for (int j = 0; j < 8; j++)
                    acc[i][j] = fmaf(a_[i], b_[j], acc[i][j]);
        }
    }

    const int hoff = g_off[e];
#pragma unroll
    for (int i = 0; i < 8; i++) {
        int m = mbase + ty * 8 + i;
        if (m < cnt) {
            float* hr = g_h + (size_t)(hoff + m) * FF + nbase;
#pragma unroll
            for (int j = 0; j < 8; j++) {
                int n = tx * 8 + j;
                float v = acc[i][j] + b1[e * FF + nbase + n];
                hr[n] = 0.5f * v * (1.f + erff(v * 0.70710678118654752f));
            }
        }
    }
}

// ---------------------------------------------------------------
// GEMM2 + bias + gate-weighted scatter: out[tok] += w*(h@W2[e]+b2[e])
// ---------------------------------------------------------------
__global__ __launch_bounds__(256)
void ffn2_kernel(const float* __restrict__ W2,
                 const float* __restrict__ b2,
                 float* __restrict__ out) {
    const int e     = blockIdx.z;
    const int cnt   = g_cnt[e];
    const int mbase = blockIdx.y * 128;
    if (mbase >= cnt) return;
    const int nbase = blockIdx.x * 128;

    __shared__ int   stok[128];
    __shared__ float swt[128];
    __shared__ float As[8][129];
    __shared__ float Bs[8][128];

    const int tid = threadIdx.x;
    if (tid < 128) {
        int mi = mbase + tid;
        bool v = mi < cnt;
        stok[tid] = v ? g_tok[e * NT + mi] : 0;
        swt[tid]  = v ? g_w  [e * NT + mi] : 0.f;
    }
    __syncthreads();

    const int tx = tid & 15, ty = tid >> 4;
    float acc[8][8];
#pragma unroll
    for (int i = 0; i < 8; i++)
#pragma unroll
        for (int j = 0; j < 8; j++) acc[i][j] = 0.f;

    const int am = tid >> 1;
    const int ak = (tid & 1) * 4;
    const int bk = tid >> 5;
    const int bn = (tid & 31) * 4;
    const int hoff = g_off[e];
    const size_t arow = (size_t)(hoff + mbase + am) * FF;  // padded scratch: in-bounds
    const float* W2e = W2 + (size_t)e * FF * DM;

    for (int kt = 0; kt < FF; kt += 8) {
        float4 av = *(const float4*)(g_h + arow + kt + ak);
        float4 bv = *(const float4*)(W2e + (size_t)(kt + bk) * DM + nbase + bn);
        __syncthreads();
        As[ak + 0][am] = av.x; As[ak + 1][am] = av.y;
        As[ak + 2][am] = av.z; As[ak + 3][am] = av.w;
        *(float4*)&Bs[bk][bn] = bv;
        __syncthreads();
#pragma unroll
        for (int kk = 0; kk < 8; kk++) {
            float a_[8], b_[8];
#pragma unroll
            for (int i = 0; i < 8; i++) a_[i] = As[kk][ty * 8 + i];
#pragma unroll
            for (int j = 0; j < 8; j++) b_[j] = Bs[kk][tx * 8 + j];
#pragma unroll
            for (int i = 0; i < 8; i++)
#pragma unroll
                for (int j = 0; j < 8; j++)
                    acc[i][j] = fmaf(a_[i], b_[j], acc[i][j]);
        }
    }

#pragma unroll
    for (int i = 0; i < 8; i++) {
        int mloc = ty * 8 + i;
        int m = mbase + mloc;
        if (m < cnt) {
            int   tok = stok[mloc];
            float wv  = swt[mloc];
            float* orow = out + (size_t)tok * DM;
#pragma unroll
            for (int j = 0; j < 8; j++) {
                int n = nbase + tx * 8 + j;
                atomicAdd(&orow[n], wv * (acc[i][j] + b2[e * DM + n]));
            }
        }
    }
}

// ---------------------------------------------------------------
extern "C" void kernel_launch(void* const* d_in, const int* in_sizes, int n_in,
                              void* d_out, int out_size) {
    const float* x  = (const float*)d_in[0];
    const float* Wg = (const float*)d_in[1];
    const float* bg = (const float*)d_in[2];
    const float* W1 = (const float*)d_in[3];
    const float* b1 = (const float*)d_in[4];
    const float* W2 = (const float*)d_in[5];
    const float* b2 = (const float*)d_in[6];
    float* out = (float*)d_out;

    zero_kernel<<<8192, 256>>>(out);
    gate_kernel<<<1024, 256>>>(x, Wg, bg);
    offsets_kernel<<<1, 32>>>();
    ffn1_kernel<<<dim3(FF / 128, NT / 128, NE), 256>>>(x, W1, b1);
    ffn2_kernel<<<dim3(DM / 128, NT / 128, NE), 256>>>(W2, b2, out);
}

// round 7
// speedup vs baseline: 1.7177x; 1.7177x over previous
#include <cuda_runtime.h>
#include <cuda_bf16.h>
#include <math.h>
#include <stdint.h>

#define NT 8192
#define DM 1024
#define FF 4096
#define NE 8
#define TOTAL_ROWS (NT * 2)

// smem geometry (floats): header 384, A [128][40], B [32][132]
#define SA 40
#define SB 132
#define HDR 384
#define SMEM_FLOATS (HDR + 128 * SA + 32 * SB)   // 9504 floats = 38016 B (<48KB, no opt-in)

// ---------------- scratch (device globals; no runtime alloc) ----------------
__device__ int   g_cnt[NE];
__device__ int   g_off[NE];
__device__ int   g_tok[NE * NT];
__device__ float g_w  [NE * NT];
// padded by 128 rows so OOB-tile A loads in GEMM2 stay in-bounds
__device__ __align__(16) float g_h[(size_t)(TOTAL_ROWS + 128) * FF];

// ---------------- mma.sync (the ONE new mechanism vs R1) ----------------
__device__ __forceinline__ void mma_bf16(float (&d)[4], const uint32_t (&a)[4],
                                         uint32_t b0, uint32_t b1) {
    asm volatile("mma.sync.aligned.m16n8k16.row.col.f32.bf16.bf16.f32 "
        "{%0,%1,%2,%3}, {%4,%5,%6,%7}, {%8,%9}, {%0,%1,%2,%3};"
        : "+f"(d[0]), "+f"(d[1]), "+f"(d[2]), "+f"(d[3])
        : "r"(a[0]), "r"(a[1]), "r"(a[2]), "r"(a[3]), "r"(b0), "r"(b1));
}

// split two fp32 into packed bf16x2 hi and lo (v = hi + lo to ~16-bit mantissa)
__device__ __forceinline__ void split2(float v0, float v1, uint32_t& hi, uint32_t& lo) {
    __nv_bfloat162 h = __floats2bfloat162_rn(v0, v1);   // .x = v0 (low half)
    float r0 = v0 - __bfloat162float(h.x);
    float r1 = v1 - __bfloat162float(h.y);
    __nv_bfloat162 l = __floats2bfloat162_rn(r0, r1);
    hi = *reinterpret_cast<uint32_t*>(&h);
    lo = *reinterpret_cast<uint32_t*>(&l);
}

// ---------------- zero counts + output ----------------
__global__ void zero_kernel(float* __restrict__ out) {
    int i = blockIdx.x * blockDim.x + threadIdx.x;
    if (i < NE) g_cnt[i] = 0;
    float4* o4 = reinterpret_cast<float4*>(out);
    if (i < NT * DM / 4) o4[i] = make_float4(0.f, 0.f, 0.f, 0.f);
}

// ---------------- gate (validated in R1) ----------------
__global__ void gate_kernel(const float* __restrict__ x,
                            const float* __restrict__ Wg,
                            const float* __restrict__ bg) {
    int gtid = blockIdx.x * blockDim.x + threadIdx.x;
    int t = gtid >> 5, lane = gtid & 31;
    if (t >= NT) return;
    const float* xr = x + (size_t)t * DM;
    float acc[NE];
#pragma unroll
    for (int e = 0; e < NE; e++) acc[e] = 0.f;
    for (int k = lane; k < DM; k += 32) {
        float xv = xr[k];
        const float* wr = Wg + k * NE;
#pragma unroll
        for (int e = 0; e < NE; e++) acc[e] += xv * wr[e];
    }
#pragma unroll
    for (int s = 16; s > 0; s >>= 1)
#pragma unroll
        for (int e = 0; e < NE; e++) acc[e] += __shfl_xor_sync(0xffffffffu, acc[e], s);
    if (lane == 0) {
#pragma unroll
        for (int e = 0; e < NE; e++) acc[e] += bg[e];
        float mx = acc[0];
#pragma unroll
        for (int e = 1; e < NE; e++) mx = fmaxf(mx, acc[e]);
        float s = 0.f;
#pragma unroll
        for (int e = 0; e < NE; e++) { acc[e] = expf(acc[e] - mx); s += acc[e]; }
        float inv = 1.f / s;
#pragma unroll
        for (int e = 0; e < NE; e++) acc[e] *= inv;
        int i0 = 0;
#pragma unroll
        for (int e = 1; e < NE; e++) if (acc[e] > acc[i0]) i0 = e;
        int i1 = (i0 == 0) ? 1 : 0;
#pragma unroll
        for (int e = 0; e < NE; e++) if (e != i0 && acc[e] > acc[i1]) i1 = e;
        float s2 = acc[i0] + acc[i1] + 1e-9f;
        int p0 = atomicAdd(&g_cnt[i0], 1);
        g_tok[i0 * NT + p0] = t;  g_w[i0 * NT + p0] = acc[i0] / s2;
        int p1 = atomicAdd(&g_cnt[i1], 1);
        g_tok[i1 * NT + p1] = t;  g_w[i1 * NT + p1] = acc[i1] / s2;
    }
}

__global__ void offsets_kernel() {
    if (threadIdx.x == 0 && blockIdx.x == 0) {
        int s = 0;
#pragma unroll
        for (int e = 0; e < NE; e++) { g_off[e] = s; s += g_cnt[e]; }
    }
}

// ---- shared compute: one k32 smem stage -> 48x2 MMAs with on-the-fly split ----
__device__ __forceinline__ void compute_stage(const float* __restrict__ As,
                                              const float* __restrict__ Bs,
                                              int wm, int wn, int lid,
                                              float (&acc)[2][8][4]) {
    const int qr = lid >> 2;            // lane row/col group
    const int c2 = (lid & 3) * 2;       // k pair base
#pragma unroll
    for (int s = 0; s < 2; s++) {
        const int kk = s * 16 + c2;
        uint32_t ah[2][4], al[2][4];
#pragma unroll
        for (int mf = 0; mf < 2; mf++) {
            const int r = wm + mf * 16 + qr;
            float2 p0 = *reinterpret_cast<const float2*>(&As[r * SA + kk]);
            float2 p1 = *reinterpret_cast<const float2*>(&As[(r + 8) * SA + kk]);
            float2 p2 = *reinterpret_cast<const float2*>(&As[r * SA + kk + 8]);
            float2 p3 = *reinterpret_cast<const float2*>(&As[(r + 8) * SA + kk + 8]);
            split2(p0.x, p0.y, ah[mf][0], al[mf][0]);
            split2(p1.x, p1.y, ah[mf][1], al[mf][1]);
            split2(p2.x, p2.y, ah[mf][2], al[mf][2]);
            split2(p3.x, p3.y, ah[mf][3], al[mf][3]);
        }
#pragma unroll
        for (int g = 0; g < 8; g++) {
            const int n = wn + g * 8 + qr;
            float b00 = Bs[kk * SB + n];
            float b01 = Bs[(kk + 1) * SB + n];
            float b10 = Bs[(kk + 8) * SB + n];
            float b11 = Bs[(kk + 9) * SB + n];
            uint32_t bh0, bl0, bh1, bl1;
            split2(b00, b01, bh0, bl0);
            split2(b10, b11, bh1, bl1);
#pragma unroll
            for (int mf = 0; mf < 2; mf++) {
                mma_bf16(acc[mf][g], ah[mf], bh0, bh1);   // hi*hi
                mma_bf16(acc[mf][g], al[mf], bh0, bh1);   // lo*hi
                mma_bf16(acc[mf][g], ah[mf], bl0, bl1);   // hi*lo
            }
        }
    }
}

// ================= GEMM1: h = gelu(x[tok] @ W1[:, n] + b1) =================
__global__ __launch_bounds__(256, 2) void ffn1_hmma(const float* __restrict__ x,
                                                    const float* __restrict__ W1,
                                                    const float* __restrict__ b1) {
    extern __shared__ float sm[];
    const int e = blockIdx.z;
    const int cnt = g_cnt[e];
    const int mbase = blockIdx.y * 128;
    if (mbase >= cnt) return;
    const int nbase = blockIdx.x * 128;

    const int tid = threadIdx.x, wid = tid >> 5, lid = tid & 31;
    const int wm = (wid & 3) * 32, wn = (wid >> 2) * 64;

    int*   stok  = reinterpret_cast<int*>(sm);   // [0..127]
    float* sbias = sm + 128;                     // [128..255]
    float* As = sm + HDR;                        // [128][SA]
    float* Bs = As + 128 * SA;                   // [32][SB]

    if (tid < 128) {
        int mi = mbase + tid;
        stok[tid]  = (mi < cnt) ? g_tok[e * NT + mi] : g_tok[e * NT + mbase];
        sbias[tid] = b1[e * FF + nbase + tid];
    }
    __syncthreads();

    const int am = tid >> 1, ak = (tid & 1) * 16;     // A: 2 threads/row, 16 k each
    const int bk = tid >> 3, bn = (tid & 7) * 16;     // B: 8 threads/row, 16 n each
    const float* xrow = x + (size_t)stok[am] * DM + ak;
    const float* wrow = W1 + (size_t)e * DM * FF + (size_t)bk * FF + nbase + bn;

    float acc[2][8][4];
#pragma unroll
    for (int i = 0; i < 2; i++)
#pragma unroll
        for (int j = 0; j < 8; j++)
#pragma unroll
            for (int k = 0; k < 4; k++) acc[i][j][k] = 0.f;

    for (int kt = 0; kt < DM; kt += 32) {
#pragma unroll
        for (int j = 0; j < 4; j++)
            *reinterpret_cast<float4*>(&As[am * SA + ak + j * 4]) =
                *reinterpret_cast<const float4*>(xrow + kt + j * 4);
#pragma unroll
        for (int j = 0; j < 4; j++)
            *reinterpret_cast<float4*>(&Bs[bk * SB + bn + j * 4]) =
                *reinterpret_cast<const float4*>(wrow + (size_t)kt * FF + j * 4);
        __syncthreads();
        compute_stage(As, Bs, wm, wn, lid, acc);
        __syncthreads();
    }

    // epilogue: bias + exact GELU -> fp32 h
    const int hoff = g_off[e];
    const int qr = lid >> 2, c2 = (lid & 3) * 2;
#pragma unroll
    for (int mf = 0; mf < 2; mf++)
#pragma unroll
        for (int half = 0; half < 2; half++) {
            int m = mbase + wm + mf * 16 + qr + half * 8;
            if (m < cnt) {
                float* hr = g_h + (size_t)(hoff + m) * FF + nbase;
#pragma unroll
                for (int g = 0; g < 8; g++) {
                    int cl = wn + g * 8 + c2;
                    float v0 = acc[mf][g][half * 2]     + sbias[cl];
                    float v1 = acc[mf][g][half * 2 + 1] + sbias[cl + 1];
                    hr[cl]     = 0.5f * v0 * (1.f + erff(v0 * 0.70710678118654752f));
                    hr[cl + 1] = 0.5f * v1 * (1.f + erff(v1 * 0.70710678118654752f));
                }
            }
        }
}

// ================= GEMM2: out[tok] += w * (h @ W2[:, n] + b2) =================
__global__ __launch_bounds__(256, 2) void ffn2_hmma(const float* __restrict__ W2,
                                                    const float* __restrict__ b2,
                                                    float* __restrict__ out) {
    extern __shared__ float sm[];
    const int e = blockIdx.z;
    const int cnt = g_cnt[e];
    const int mbase = blockIdx.y * 128;
    if (mbase >= cnt) return;
    const int nbase = blockIdx.x * 128;

    const int tid = threadIdx.x, wid = tid >> 5, lid = tid & 31;
    const int wm = (wid & 3) * 32, wn = (wid >> 2) * 64;

    int*   stok  = reinterpret_cast<int*>(sm);
    float* sbias = sm + 128;
    float* swt   = sm + 256;
    float* As = sm + HDR;
    float* Bs = As + 128 * SA;

    if (tid < 128) {
        int mi = mbase + tid;
        bool v = mi < cnt;
        stok[tid]  = v ? g_tok[e * NT + mi] : 0;
        swt[tid]   = v ? g_w  [e * NT + mi] : 0.f;
        sbias[tid] = b2[e * DM + nbase + tid];
    }
    __syncthreads();

    const int hoff = g_off[e];
    const int am = tid >> 1, ak = (tid & 1) * 16;
    const int bk = tid >> 3, bn = (tid & 7) * 16;
    const float* arow = g_h + (size_t)(hoff + mbase + am) * FF + ak;   // padded scratch
    const float* wrow = W2 + (size_t)e * FF * DM + (size_t)bk * DM + nbase + bn;

    float acc[2][8][4];
#pragma unroll
    for (int i = 0; i < 2; i++)
#pragma unroll
        for (int j = 0; j < 8; j++)
#pragma unroll
            for (int k = 0; k < 4; k++) acc[i][j][k] = 0.f;

    for (int kt = 0; kt < FF; kt += 32) {
#pragma unroll
        for (int j = 0; j < 4; j++)
            *reinterpret_cast<float4*>(&As[am * SA + ak + j * 4]) =
                *reinterpret_cast<const float4*>(arow + kt + j * 4);
#pragma unroll
        for (int j = 0; j < 4; j++)
            *reinterpret_cast<float4*>(&Bs[bk * SB + bn + j * 4]) =
                *reinterpret_cast<const float4*>(wrow + (size_t)kt * DM + j * 4);
        __syncthreads();
        compute_stage(As, Bs, wm, wn, lid, acc);
        __syncthreads();
    }

    // epilogue: bias + gate-weighted scatter
    const int qr = lid >> 2, c2 = (lid & 3) * 2;
#pragma unroll
    for (int mf = 0; mf < 2; mf++)
#pragma unroll
        for (int half = 0; half < 2; half++) {
            int mloc = wm + mf * 16 + qr + half * 8;
            int m = mbase + mloc;
            if (m < cnt) {
                int   tok = stok[mloc];
                float wv  = swt[mloc];
                float* orow = out + (size_t)tok * DM + nbase;
#pragma unroll
                for (int g = 0; g < 8; g++) {
                    int cl = wn + g * 8 + c2;
                    atomicAdd(&orow[cl],     wv * (acc[mf][g][half * 2]     + sbias[cl]));
                    atomicAdd(&orow[cl + 1], wv * (acc[mf][g][half * 2 + 1] + sbias[cl + 1]));
                }
            }
        }
}

// ---------------------------------------------------------------
extern "C" void kernel_launch(void* const* d_in, const int* in_sizes, int n_in,
                              void* d_out, int out_size) {
    const float* x  = (const float*)d_in[0];
    const float* Wg = (const float*)d_in[1];
    const float* bg = (const float*)d_in[2];
    const float* W1 = (const float*)d_in[3];
    const float* b1 = (const float*)d_in[4];
    const float* W2 = (const float*)d_in[5];
    const float* b2 = (const float*)d_in[6];
    float* out = (float*)d_out;

    const int smem_bytes = SMEM_FLOATS * 4;   // 38016 < 48KB: no attribute needed

    zero_kernel<<<NT * DM / 4 / 256, 256>>>(out);
    gate_kernel<<<1024, 256>>>(x, Wg, bg);
    offsets_kernel<<<1, 32>>>();
    ffn1_hmma<<<dim3(FF / 128, NT / 128, NE), 256, smem_bytes>>>(x, W1, b1);
    ffn2_hmma<<<dim3(DM / 128, NT / 128, NE), 256, smem_bytes>>>(W2, b2, out);
}